// round 5
// baseline (speedup 1.0000x reference)
#include <cuda_runtime.h>

#define NTOT  22743
#define NB    64
#define TOTAL (NB * NTOT)
#define CAP   8192
#define NEGF  -1e9f

#define BLKA  256
#define RPT   8
#define CHUNK (BLKA * RPT)

typedef unsigned long long ull;

// per-image compacted candidate keys: (score_bits << 32) | ~anchor_idx
__device__ ull g_cand[(size_t)NB * CAP];
__device__ int g_cnt[NB];             // zeroed at init; kernel B resets after use
__device__ int g_hist[NB * 1024];     // per-image score-bucket histogram

// anchors in pixels: level*3 + a  (w, h)
__constant__ float c_aw[9] = {116.f, 156.f, 373.f,  30.f, 62.f, 59.f,  10.f, 16.f, 33.f};
__constant__ float c_ah[9] = { 90.f, 198.f, 326.f,  61.f, 45.f, 119.f, 13.f, 30.f, 23.f};

__device__ __forceinline__ const float* rec_ptrf(const float* p0, const float* p1,
                                                 const float* p2, int b, int n) {
    if (n < 1083)  return p0 + ((size_t)b * 1083 + n) * 26;
    if (n < 5415)  return p1 + ((size_t)b * 4332 + (n - 1083)) * 26;
    return p2 + ((size_t)b * 17328 + (n - 5415)) * 26;
}

__device__ __forceinline__ int bucket_of(unsigned score_bits) {
    return min(max((int)(score_bits >> 15) - 0x7C00, 0), 1023);
}

// push one candidate (warp-aggregated per image) + histogram RED
__device__ __forceinline__ void push_cand(int b, int n, float sc, int lane) {
    unsigned am = __activemask();
    unsigned mb = __match_any_sync(am, b);
    unsigned grp = mb & am;
    int leader = __ffs(grp) - 1;
    int rank = __popc(grp & ((1u << lane) - 1u));
    int bp = 0;
    if (lane == leader) bp = atomicAdd(&g_cnt[b], __popc(grp));
    bp = __shfl_sync(grp, bp, leader);
    int p = bp + rank;
    unsigned sb = __float_as_uint(sc);
    if (p < CAP)
        g_cand[(size_t)b * CAP + p] = ((ull)sb << 32) | (unsigned)(~(unsigned)n);
    atomicAdd(&g_hist[b * 1024 + bucket_of(sb)], 1);   // no return -> RED
}

// shared scoring epilogue: l[0..19] = class logits f6..f25 in order
__device__ __forceinline__ void score_epilogue(int b, int n, float gx, float gy,
                                               const float* l, int lane) {
    float mx = l[0];
#pragma unroll
    for (int k = 1; k < 20; k++) mx = fmaxf(mx, l[k]);
    float ssum = 0.f;
#pragma unroll
    for (int k = 0; k < 20; k++) ssum += __expf(l[k] - mx);
    float obj = __fdividef(1.f, 1.f + __expf(-gx));
    float conf = __fdividef(obj, ssum);                // obj * max(softmax)
    float sc = NEGF;
    if (conf >= 0.05f) {
        float loc = __fdividef(1.f, 1.f + __expf(-gy));
        sc = sqrtf(conf) * sqrtf(loc);
    }
    bool push = sc > 0.f;
    // two-phase: ballot first so push_cand's activemask is the pushing set
    if (push) push_cand(b, n, sc, lane);
}

// ---------------------------------------------------------------------------
// Kernel A: batched gate loads (MLP=8) -> parity-split smem work queues ->
// dense vectorized softmax. Gate on raw logits (no transcendentals).
// ---------------------------------------------------------------------------
__global__ __launch_bounds__(BLKA) void score_kernel(
    const float* __restrict__ p0, const float* __restrict__ p1,
    const float* __restrict__ p2) {

    __shared__ int q[CHUNK];      // even-aligned grows from 0, odd from CHUNK-1
    __shared__ int qe, qo;

    int tid = threadIdx.x;
    int lane = tid & 31;
    if (tid == 0) { qe = 0; qo = 0; }
    __syncthreads();

    int base = blockIdx.x * CHUNK;

    // ---- phase 1: 8 independent gate loads per thread ----
    float2 gate[RPT];
    int idx[RPT];
    bool al16[RPT];
#pragma unroll
    for (int r = 0; r < RPT; r++) {
        int t = base + r * BLKA + tid;
        idx[r] = t;
        if (t < TOTAL) {
            int b = t / NTOT;
            int n = t - b * NTOT;
            const float* rp = rec_ptrf(p0, p1, p2, b, n);
            al16[r] = (((size_t)rp & 15) == 0);
            gate[r] = __ldg((const float2*)(rp + 4));
        } else {
            gate[r] = make_float2(NEGF, NEGF);
            al16[r] = true;
        }
    }

    // obj >= 0.6 <=> logit >= ln(1.5); loc >= 0.5 <=> logit >= 0
#pragma unroll
    for (int r = 0; r < RPT; r++) {
        bool pass = (idx[r] < TOTAL) &&
                    (gate[r].x >= 0.40546510810816444f) && (gate[r].y >= 0.0f);
        unsigned mE = __ballot_sync(0xFFFFFFFFu, pass && al16[r]);
        unsigned mO = __ballot_sync(0xFFFFFFFFu, pass && !al16[r]);
        if (pass && al16[r]) {
            int leader = __ffs(mE) - 1;
            int rank = __popc(mE & ((1u << lane) - 1u));
            int bp = 0;
            if (lane == leader) bp = atomicAdd(&qe, __popc(mE));
            bp = __shfl_sync(mE, bp, leader);
            q[bp + rank] = idx[r];
        }
        if (pass && !al16[r]) {
            int leader = __ffs(mO) - 1;
            int rank = __popc(mO & ((1u << lane) - 1u));
            int bp = 0;
            if (lane == leader) bp = atomicAdd(&qo, __popc(mO));
            bp = __shfl_sync(mO, bp, leader);
            q[CHUNK - 1 - (bp + rank)] = idx[r];
        }
    }
    __syncthreads();

    int ne = qe, no = qo;

    // ---- phase 2a: 16B-aligned records (6 vector loads) ----
    for (int i = tid; i < ne; i += BLKA) {
        int t = q[i];
        int b = t / NTOT;
        int n = t - b * NTOT;
        const float* rec = rec_ptrf(p0, p1, p2, b, n);
        const float4* r4 = (const float4*)(rec + 4);          // aligned
        float4 a0 = __ldg(r4);          // f4 f5 f6 f7
        float4 a1 = __ldg(r4 + 1);      // f8..f11
        float4 a2 = __ldg(r4 + 2);
        float4 a3 = __ldg(r4 + 3);
        float4 a4 = __ldg(r4 + 4);      // f20..f23
        float2 a5 = __ldg((const float2*)(rec + 24));
        float l[20] = {a0.z, a0.w, a1.x, a1.y, a1.z, a1.w, a2.x, a2.y, a2.z, a2.w,
                       a3.x, a3.y, a3.z, a3.w, a4.x, a4.y, a4.z, a4.w, a5.x, a5.y};
        score_epilogue(b, n, a0.x, a0.y, l, lane);
    }

    // ---- phase 2b: 8-mod-16 records (rec+6 is aligned; 6 vector loads) ----
    for (int i = tid; i < no; i += BLKA) {
        int t = q[CHUNK - 1 - i];
        int b = t / NTOT;
        int n = t - b * NTOT;
        const float* rec = rec_ptrf(p0, p1, p2, b, n);
        float2 g = __ldg((const float2*)(rec + 4));
        const float4* r4 = (const float4*)(rec + 6);          // aligned
        float4 a0 = __ldg(r4);
        float4 a1 = __ldg(r4 + 1);
        float4 a2 = __ldg(r4 + 2);
        float4 a3 = __ldg(r4 + 3);
        float4 a4 = __ldg(r4 + 4);
        float l[20] = {a0.x, a0.y, a0.z, a0.w, a1.x, a1.y, a1.z, a1.w, a2.x, a2.y,
                       a2.z, a2.w, a3.x, a3.y, a3.z, a3.w, a4.x, a4.y, a4.z, a4.w};
        score_epilogue(b, n, g.x, g.y, l, lane);
    }
}

// ---------------------------------------------------------------------------
// Kernel B: one block per image. Radix-select (precomputed histogram +
// warp-shuffle suffix scan) -> low-barrier bitonic sort -> vectorized decode
// -> per-class parallel soft-NMS (one warp per class) -> parallel top-8 out.
// ---------------------------------------------------------------------------
__global__ __launch_bounds__(1024) void select_nms_kernel(
    const float* __restrict__ p0, const float* __restrict__ p1,
    const float* __restrict__ p2, float* __restrict__ out) {

    __shared__ ull    keys2[2048];
    __shared__ int    suf[1024];
    __shared__ int    wsum[32];
    __shared__ int    wsuf[32];
    __shared__ float4 cbox[256];
    __shared__ float  cval[256];
    __shared__ float  carea[256];
    __shared__ int    ccls[256];
    __shared__ unsigned char kept[256];
    __shared__ unsigned char clist[20][64];
    __shared__ unsigned kmask[8];
    __shared__ int s_T, s_col, s_cnt;

    int tid = threadIdx.x;
    int lane = tid & 31;
    int w = tid >> 5;
    int b = blockIdx.x;

    if (tid == 0) {
        s_cnt = min(g_cnt[b], CAP);
        g_cnt[b] = 0;                        // reset for next call (graph-safe)
        s_col = 0;
        s_T = 0;
    }
    int hv = g_hist[b * 1024 + tid];         // histogram built by kernel A
    g_hist[b * 1024 + tid] = 0;              // reset for next call
    if (tid < 256) kept[tid] = 0;
    __syncthreads();

    int cnt = s_cnt;
    const ull* cand = g_cand + (size_t)b * CAP;

    // ---- suffix scan via warp shuffles ----
    int v = hv;
#pragma unroll
    for (int s = 1; s < 32; s <<= 1) {
        int t2 = __shfl_down_sync(0xFFFFFFFFu, v, s);
        if (lane + s < 32) v += t2;
    }
    if (lane == 0) wsum[w] = v;              // chunk total (suffix at lane 0)
    __syncthreads();
    if (w == 0) {
        int x = wsum[lane];
        int tot0 = x;
#pragma unroll
        for (int s = 1; s < 32; s <<= 1) {
            int t2 = __shfl_down_sync(0xFFFFFFFFu, x, s);
            if (lane + s < 32) x += t2;
        }
        wsuf[lane] = x - tot0;               // exclusive suffix of later warps
    }
    __syncthreads();
    int sufv = v + wsuf[w];
    suf[tid] = sufv;
    __syncthreads();
    // threshold bucket T: largest i with suffix[i] >= 256 (0 if total < 256)
    if (sufv >= 256 && (tid == 1023 || suf[tid + 1] < 256)) s_T = tid;
    __syncthreads();
    int T = s_T;

    // ---- compact entries in buckets >= T ----
    for (int i = tid; i < cnt; i += 1024) {
        ull k = __ldg(cand + i);
        int bk = bucket_of((unsigned)(k >> 32));
        if (bk >= T) {
            int p = atomicAdd(&s_col, 1);
            if (p < 2048) keys2[p] = k;
        }
    }
    __syncthreads();
    int col = min(s_col, 2048);
    int n2 = 256;
    while (n2 < col) n2 <<= 1;
    for (int i = col + tid; i < n2; i += 1024) keys2[i] = 0ULL;
    __syncthreads();

    // ---- bitonic sort (descending); j<32 passes are warp-local ----
    for (int k = 2; k <= n2; k <<= 1) {
        for (int j = k >> 1; j > 0; j >>= 1) {
            for (int i = tid; i < n2; i += 1024) {
                int l = i ^ j;
                if (l > i) {
                    ull a = keys2[i], c2 = keys2[l];
                    bool desc = ((i & k) == 0);
                    if ((a < c2) == desc) { keys2[i] = c2; keys2[l] = a; }
                }
            }
            if (j >= 32) __syncthreads(); else __syncwarp();
        }
    }
    __syncthreads();

    // ---- decode top-256 candidates (vectorized loads) ----
    if (tid < 256) {
        ull kk = keys2[tid];
        float4 bx = make_float4(0.f, 0.f, 0.f, 0.f);
        int cls = 255;               // never matches a class warp (0..19)
        float val = NEGF;
        float area = 0.f;
        if (kk != 0ULL) {
            unsigned n = ~(unsigned)(kk & 0xFFFFFFFFull);
            val = __uint_as_float((unsigned)(kk >> 32));
            int lvl, r, GG, G; float strd; const float* base;
            if (n < 1083u) {
                lvl = 0; r = (int)n;        GG = 361;  G = 19; strd = 32.f;
                base = p0 + (size_t)b * 1083 * 26;
            } else if (n < 5415u) {
                lvl = 1; r = (int)n - 1083; GG = 1444; G = 38; strd = 16.f;
                base = p1 + (size_t)b * 4332 * 26;
            } else {
                lvl = 2; r = (int)n - 5415; GG = 5776; G = 76; strd = 8.f;
                base = p2 + (size_t)b * 17328 * 26;
            }
            int a = r / GG; int cell = r - a * GG;
            int gy = cell / G; int gx = cell - gy * G;
            const float* rec = base + (size_t)r * 26;
            float tx, ty, tw, th, cl[20];
            if (((size_t)rec & 15) == 0) {
                float4 q0 = __ldg((const float4*)rec);            // f0..3
                float4 q1 = __ldg((const float4*)(rec + 4));      // f4..7
                float4 q2 = __ldg((const float4*)(rec + 8));
                float4 q3 = __ldg((const float4*)(rec + 12));
                float4 q4 = __ldg((const float4*)(rec + 16));
                float4 q5 = __ldg((const float4*)(rec + 20));     // f20..23
                float2 q6 = __ldg((const float2*)(rec + 24));
                tx = q0.x; ty = q0.y; tw = q0.z; th = q0.w;
                cl[0] = q1.z;  cl[1] = q1.w;
                cl[2] = q2.x;  cl[3] = q2.y;  cl[4] = q2.z;  cl[5] = q2.w;
                cl[6] = q3.x;  cl[7] = q3.y;  cl[8] = q3.z;  cl[9] = q3.w;
                cl[10] = q4.x; cl[11] = q4.y; cl[12] = q4.z; cl[13] = q4.w;
                cl[14] = q5.x; cl[15] = q5.y; cl[16] = q5.z; cl[17] = q5.w;
                cl[18] = q6.x; cl[19] = q6.y;
            } else {
                float2 q0 = __ldg((const float2*)rec);            // f0,f1
                float4 q1 = __ldg((const float4*)(rec + 2));      // f2..5
                float4 q2 = __ldg((const float4*)(rec + 6));      // f6..9
                float4 q3 = __ldg((const float4*)(rec + 10));
                float4 q4 = __ldg((const float4*)(rec + 14));
                float4 q5 = __ldg((const float4*)(rec + 18));     // f18..21
                float4 q6 = __ldg((const float4*)(rec + 22));     // f22..25
                tx = q0.x; ty = q0.y; tw = q1.x; th = q1.y;
                cl[0] = q2.x;  cl[1] = q2.y;  cl[2] = q2.z;  cl[3] = q2.w;
                cl[4] = q3.x;  cl[5] = q3.y;  cl[6] = q3.z;  cl[7] = q3.w;
                cl[8] = q4.x;  cl[9] = q4.y;  cl[10] = q4.z; cl[11] = q4.w;
                cl[12] = q5.x; cl[13] = q5.y; cl[14] = q5.z; cl[15] = q5.w;
                cl[16] = q6.x; cl[17] = q6.y; cl[18] = q6.z; cl[19] = q6.w;
            }
            float m = cl[0]; int ci = 0;
#pragma unroll
            for (int c = 1; c < 20; c++)
                if (cl[c] > m) { m = cl[c]; ci = c; }
            float sx = __fdividef(1.f, 1.f + __expf(-tx));
            float sy = __fdividef(1.f, 1.f + __expf(-ty));
            float cx = (sx + (float)gx) * strd;
            float cy = (sy + (float)gy) * strd;
            float ww2 = __expf(tw) * c_aw[lvl * 3 + a];
            float hh = __expf(th) * c_ah[lvl * 3 + a];
            float x1 = fminf(fmaxf(cx - 0.5f * ww2, 0.f), 608.f);
            float y1 = fminf(fmaxf(cy - 0.5f * hh, 0.f), 608.f);
            float x2 = fminf(fmaxf(cx + 0.5f * ww2, 0.f), 608.f);
            float y2 = fminf(fmaxf(cy + 0.5f * hh, 0.f), 608.f);
            bx = make_float4(x1, y1, x2, y2);
            area = (x2 - x1 + 1.f) * (y2 - y1 + 1.f);
            cls = ci;
        }
        cbox[tid] = bx;
        cval[tid] = val;
        carea[tid] = area;
        ccls[tid] = cls;
    }
    __syncthreads();

    // ---- per-class soft-NMS: warp w handles class w (classes decouple) ----
    if (w < 20) {
        int c = w;
        int cntc = 0;
        for (int g = 0; g < 8; g++) {
            int ci2 = g * 32 + lane;
            bool take = (ccls[ci2] == c);
            unsigned mm = __ballot_sync(0xFFFFFFFFu, take);
            if (take) {
                int pos = cntc + __popc(mm & ((1u << lane) - 1u));
                if (pos < 64) clist[c][pos] = (unsigned char)ci2;
            }
            cntc += __popc(mm);
        }
        if (cntc > 64) cntc = 64;
        __syncwarp();

        int cand0 = (lane < cntc) ? (int)clist[c][lane] : -1;
        int cand1 = (lane + 32 < cntc) ? (int)clist[c][lane + 32] : -1;
        float s0f = (cand0 >= 0) ? cval[cand0] : NEGF;
        float s1f = (cand1 >= 0) ? cval[cand1] : NEGF;
        float4 b0 = (cand0 >= 0) ? cbox[cand0] : make_float4(0.f, 0.f, 0.f, 0.f);
        float4 b1 = (cand1 >= 0) ? cbox[cand1] : make_float4(0.f, 0.f, 0.f, 0.f);
        float a0 = (cand0 >= 0) ? carea[cand0] : 0.f;
        float a1 = (cand1 >= 0) ? carea[cand1] : 0.f;

        while (true) {
            float sm; int im;
            if (s1f > s0f) { sm = s1f; im = cand1; }
            else           { sm = s0f; im = cand0; }   // tie -> lower cand idx
            unsigned kb = (sm > 0.f) ? __float_as_uint(sm) : 0u;
            unsigned gmax = __reduce_max_sync(0xFFFFFFFFu, kb);
            if (gmax < 0x3DCCCCCDu) break;             // 0.1f as bits
            int mi = (kb == gmax) ? im : 0x7FFFFFFF;
            int j = __reduce_min_sync(0xFFFFFFFFu, mi);
            if (lane == 0) kept[j] = 1;
            float4 bj = cbox[j];
            float aj = carea[j];
            if (cand0 >= 0) {
                if (cand0 == j) s0f = NEGF;
                else {
                    float ix1 = fmaxf(bj.x, b0.x), iy1 = fmaxf(bj.y, b0.y);
                    float ix2 = fminf(bj.z, b0.z), iy2 = fminf(bj.w, b0.w);
                    float inter = fmaxf(ix2 - ix1 + 1.f, 0.f) *
                                  fmaxf(iy2 - iy1 + 1.f, 0.f);
                    if (inter > 0.f) {   // exp(0)=1 exactly -> skip is exact
                        float iou = __fdividef(inter, aj + a0 - inter + 1e-16f);
                        s0f *= __expf(-2.f * iou * iou);
                    }
                }
            }
            if (cand1 >= 0) {
                if (cand1 == j) s1f = NEGF;
                else {
                    float ix1 = fmaxf(bj.x, b1.x), iy1 = fmaxf(bj.y, b1.y);
                    float ix2 = fminf(bj.z, b1.z), iy2 = fminf(bj.w, b1.w);
                    float inter = fmaxf(ix2 - ix1 + 1.f, 0.f) *
                                  fmaxf(iy2 - iy1 + 1.f, 0.f);
                    if (inter > 0.f) {
                        float iou = __fdividef(inter, aj + a1 - inter + 1e-16f);
                        s1f *= __expf(-2.f * iou * iou);
                    }
                }
            }
        }
    }
    __syncthreads();

    // ---- parallel output: rank kept candidates, write first 8 ----
    if (tid < 256) {
        unsigned bal = __ballot_sync(0xFFFFFFFFu, kept[tid] != 0);
        if (lane == 0) kmask[tid >> 5] = bal;
    }
    __syncthreads();
    if (tid < 256 && kept[tid]) {
        int pre = 0;
#pragma unroll
        for (int ww = 0; ww < 8; ww++)
            if (ww < (tid >> 5)) pre += __popc(kmask[ww]);
        pre += __popc(kmask[tid >> 5] & ((1u << lane) - 1u));
        if (pre < 8) {
            float* o = out + (size_t)b * 48 + pre * 6;
            float4 bb = cbox[tid];
            o[0] = bb.x; o[1] = bb.y; o[2] = bb.z; o[3] = bb.w;
            o[4] = cval[tid];
            o[5] = (float)ccls[tid];
        }
    }
    if (tid >= 256 && tid < 264) {
        int K = 0;
#pragma unroll
        for (int ww = 0; ww < 8; ww++) K += __popc(kmask[ww]);
        int slot = tid - 256;
        if (slot >= K) {
            float* o = out + (size_t)b * 48 + slot * 6;
#pragma unroll
            for (int q2 = 0; q2 < 6; q2++) o[q2] = 0.f;
        }
    }
}

extern "C" void kernel_launch(void* const* d_in, const int* in_sizes, int n_in,
                              void* d_out, int out_size) {
    const float* p0 = (const float*)d_in[0];
    const float* p1 = (const float*)d_in[1];
    const float* p2 = (const float*)d_in[2];
    float* out = (float*)d_out;

    int gridA = (TOTAL + CHUNK - 1) / CHUNK;
    score_kernel<<<gridA, BLKA>>>(p0, p1, p2);
    select_nms_kernel<<<NB, 1024>>>(p0, p1, p2, out);
}